// round 1
// baseline (speedup 1.0000x reference)
#include <cuda_runtime.h>

#define H 64
#define W 64
#define L 4096
#define C 64
#define NB 4

// Scratch (device globals -- allocation in kernel_launch is forbidden).
__device__ float g_M[NB][L * L];   // M, later reused for S  (256 MB)
__device__ float g_E[NB][L * L];   // exp(10*(scores-rowmax)) (256 MB)
__device__ float g_rinv[NB][L];    // 1/rowsum per p

// ---- packed fp32x2 helpers (Blackwell f32x2 pipe) ----
__device__ __forceinline__ unsigned long long pack2(float x, float y) {
    unsigned long long r;
    asm("mov.b64 %0, {%1, %2};" : "=l"(r) : "f"(x), "f"(y));
    return r;
}
__device__ __forceinline__ void fma2(unsigned long long &d, unsigned long long a,
                                     unsigned long long b) {
    asm("fma.rn.f32x2 %0, %1, %2, %3;" : "=l"(d) : "l"(a), "l"(b), "l"(d));
}

// ============================================================
// K1:  M[p,l] = sum_c f[c,p] * b[c,l]    (per batch, 4096x4096x64)
// ============================================================
__global__ __launch_bounds__(256) void k_gemm_M(const float *__restrict__ fin,
                                                const float *__restrict__ bin) {
    __shared__ float As[64][64];  // [c][p]
    __shared__ float Bs[64][64];  // [c][l]
    const int bt = blockIdx.z;
    const int p0 = blockIdx.y << 6;
    const int l0 = blockIdx.x << 6;
    const float *fb = fin + bt * (C * L);
    const float *bb = bin + bt * (C * L);
    const int tid = threadIdx.x;
#pragma unroll
    for (int i = 0; i < 16; i++) {
        int idx = tid + (i << 8);
        int c = idx >> 6, x = idx & 63;
        As[c][x] = fb[c * L + p0 + x];
        Bs[c][x] = bb[c * L + l0 + x];
    }
    __syncthreads();
    const int tx = tid & 15, ty = tid >> 4;
    unsigned long long acc[4][2] = {};
#pragma unroll 16
    for (int c = 0; c < 64; c++) {
        float4 av = *(const float4 *)&As[c][ty << 2];
        ulonglong2 bv = *(const ulonglong2 *)&Bs[c][tx << 2];
        unsigned long long a0 = pack2(av.x, av.x);
        unsigned long long a1 = pack2(av.y, av.y);
        unsigned long long a2 = pack2(av.z, av.z);
        unsigned long long a3 = pack2(av.w, av.w);
        fma2(acc[0][0], a0, bv.x); fma2(acc[0][1], a0, bv.y);
        fma2(acc[1][0], a1, bv.x); fma2(acc[1][1], a1, bv.y);
        fma2(acc[2][0], a2, bv.x); fma2(acc[2][1], a2, bv.y);
        fma2(acc[3][0], a3, bv.x); fma2(acc[3][1], a3, bv.y);
    }
    float *out = g_M[bt];
#pragma unroll
    for (int a = 0; a < 4; a++) {
        ulonglong2 v;
        v.x = acc[a][0];
        v.y = acc[a][1];
        *(ulonglong2 *)&out[(p0 + (ty << 2) + a) * L + l0 + (tx << 2)] = v;
    }
}

// ============================================================
// K2: scores[p,l] = sum_d valid(p+d)&valid(l+d) M[p+d,l+d]
//     then row softmax (over l): E = exp(10*(s - rowmax)), rinv = 1/rowsum
// ============================================================
__global__ __launch_bounds__(256) void k_score_softmax() {
    const int bt = blockIdx.y;
    const int p = blockIdx.x;
    const int py = p >> 6, px = p & 63;
    const float *__restrict__ M = g_M[bt];
    const int t = threadIdx.x;
    __shared__ float redA[8], redB[8];

    float s[16];
#pragma unroll
    for (int k = 0; k < 16; k++) {
        const int l = t + (k << 8);
        const int ly = l >> 6, lx = l & 63;
        float acc = 0.f;
#pragma unroll
        for (int dy = -1; dy <= 1; dy++) {
#pragma unroll
            for (int dx = -1; dx <= 1; dx++) {
                if ((unsigned)(py + dy) < 64u && (unsigned)(px + dx) < 64u &&
                    (unsigned)(ly + dy) < 64u && (unsigned)(lx + dx) < 64u) {
                    const int off = dy * 64 + dx;
                    acc += M[(p + off) * L + l + off];
                }
            }
        }
        s[k] = acc;
    }
    // block max over 4096 elems
    float m = s[0];
#pragma unroll
    for (int k = 1; k < 16; k++) m = fmaxf(m, s[k]);
#pragma unroll
    for (int o = 16; o; o >>= 1) m = fmaxf(m, __shfl_xor_sync(0xffffffffu, m, o));
    if ((t & 31) == 0) redA[t >> 5] = m;
    __syncthreads();
    float rowmax = redA[0];
#pragma unroll
    for (int i = 1; i < 8; i++) rowmax = fmaxf(rowmax, redA[i]);

    float sum = 0.f;
#pragma unroll
    for (int k = 0; k < 16; k++) {
        float e = __expf(10.f * (s[k] - rowmax));
        s[k] = e;
        sum += e;
    }
#pragma unroll
    for (int o = 16; o; o >>= 1) sum += __shfl_xor_sync(0xffffffffu, sum, o);
    if ((t & 31) == 0) redB[t >> 5] = sum;
    __syncthreads();

    float *E = g_E[bt] + p * L;
#pragma unroll
    for (int k = 0; k < 16; k++) E[t + (k << 8)] = s[k];

    if (t == 0) {
        float tot = 0.f;
#pragma unroll
        for (int i = 0; i < 8; i++) tot += redB[i];
        g_rinv[bt][p] = 1.f / tot;
    }
}

// ============================================================
// K3: S[p,l] = (1/9) * sum_d valid E[p+d, l+d] * rinv[p+d]   -> into g_M
// ============================================================
__global__ __launch_bounds__(256) void k_attn_S() {
    const int bt = blockIdx.y;
    const int p = blockIdx.x;
    const int py = p >> 6, px = p & 63;
    const float *__restrict__ E = g_E[bt];
    const float *__restrict__ ri = g_rinv[bt];
    const int t = threadIdx.x;

    float rv[9];
    bool pv[9];
    {
        int i = 0;
#pragma unroll
        for (int dy = -1; dy <= 1; dy++)
#pragma unroll
            for (int dx = -1; dx <= 1; dx++) {
                bool ok = (unsigned)(py + dy) < 64u && (unsigned)(px + dx) < 64u;
                pv[i] = ok;
                rv[i] = ok ? ri[p + dy * 64 + dx] : 0.f;
                i++;
            }
    }

    float *out = g_M[bt] + p * L;
#pragma unroll
    for (int k = 0; k < 16; k++) {
        const int l = t + (k << 8);
        const int ly = l >> 6, lx = l & 63;
        float acc = 0.f;
        int i = 0;
#pragma unroll
        for (int dy = -1; dy <= 1; dy++)
#pragma unroll
            for (int dx = -1; dx <= 1; dx++) {
                if (pv[i] && (unsigned)(ly + dy) < 64u && (unsigned)(lx + dx) < 64u) {
                    const int off = dy * 64 + dx;
                    acc += E[(p + off) * L + l + off] * rv[i];
                }
                i++;
            }
        out[l] = acc * (1.f / 9.f);
    }
}

// ============================================================
// K4:  y[c,p] = sum_l S[p,l] * b[c,l]    (1/9 already folded into S)
// ============================================================
__global__ __launch_bounds__(256) void k_gemm_y(const float *__restrict__ bin,
                                                float *__restrict__ yout) {
    __shared__ float Ss[64][68];  // [l][p]  (transposed, padded for 16B align)
    __shared__ float Bs[64][68];  // [l][c]
    const int bt = blockIdx.y;
    const int p0 = blockIdx.x << 6;
    const float *S = g_M[bt];
    const float *bb = bin + bt * (C * L);
    const int tid = threadIdx.x;
    const int tx = tid & 15, ty = tid >> 4;  // tx -> p, ty -> c
    unsigned long long acc[4][2] = {};

    for (int lt = 0; lt < L; lt += 64) {
        __syncthreads();
#pragma unroll
        for (int i = 0; i < 16; i++) {
            int idx = tid + (i << 8);
            int r = idx >> 6, q = idx & 63;  // r: p/c index, q: l index
            Ss[q][r] = S[(p0 + r) * L + lt + q];
            Bs[q][r] = bb[r * L + lt + q];
        }
        __syncthreads();
#pragma unroll 16
        for (int l = 0; l < 64; l++) {
            ulonglong2 sv = *(const ulonglong2 *)&Ss[l][tx << 2];
            float4 bv = *(const float4 *)&Bs[l][ty << 2];
            unsigned long long c0 = pack2(bv.x, bv.x);
            unsigned long long c1 = pack2(bv.y, bv.y);
            unsigned long long c2 = pack2(bv.z, bv.z);
            unsigned long long c3 = pack2(bv.w, bv.w);
            fma2(acc[0][0], c0, sv.x); fma2(acc[0][1], c0, sv.y);
            fma2(acc[1][0], c1, sv.x); fma2(acc[1][1], c1, sv.y);
            fma2(acc[2][0], c2, sv.x); fma2(acc[2][1], c2, sv.y);
            fma2(acc[3][0], c3, sv.x); fma2(acc[3][1], c3, sv.y);
        }
    }
    float *yb = yout + bt * (C * L);
#pragma unroll
    for (int a = 0; a < 4; a++) {
        ulonglong2 v;
        v.x = acc[a][0];
        v.y = acc[a][1];
        *(ulonglong2 *)&yb[((ty << 2) + a) * L + p0 + (tx << 2)] = v;
    }
}

// ============================================================
// K5: w output: w[b,l,c,i,j] = b[c, l + (i-1,j-1)]  (0 when OOB)
// ============================================================
__global__ __launch_bounds__(256) void k_wout(const float *__restrict__ bin,
                                              float *__restrict__ wout) {
    const int idx = blockIdx.x * 256 + threadIdx.x;  // < NB*L*C*9 exactly
    const int j3 = idx % 9;
    const int c = (idx / 9) & 63;
    const int l = (idx / 576) & 4095;
    const int bt = idx / (576 * 4096);
    const int dy = j3 / 3 - 1, dx = j3 % 3 - 1;
    const int ly = l >> 6, lx = l & 63;
    float v = 0.f;
    if ((unsigned)(ly + dy) < 64u && (unsigned)(lx + dx) < 64u)
        v = bin[bt * (C * L) + c * L + l + dy * 64 + dx];
    wout[idx] = v;
}

extern "C" void kernel_launch(void *const *d_in, const int *in_sizes, int n_in,
                              void *d_out, int out_size) {
    const float *f = (const float *)d_in[0];
    const float *b = (const float *)d_in[1];
    float *out = (float *)d_out;

    k_gemm_M<<<dim3(64, 64, NB), 256>>>(f, b);
    k_score_softmax<<<dim3(L, NB), 256>>>();
    k_attn_S<<<dim3(L, NB), 256>>>();
    k_gemm_y<<<dim3(64, NB), 256>>>(b, out);
    // w part starts right after y (NB*C*L floats)
    k_wout<<<(NB * L * C * 9) / 256, 256>>>(b, out + NB * C * L);
}